// round 4
// baseline (speedup 1.0000x reference)
#include <cuda_runtime.h>
#include <cstddef>

// N=8192, D=2, L=1.0, R0=0.1, no self-loop.
// Output: [0, N*N) dist (f32, row-major), [N*N, 2*N*N) mask as 0.0/1.0.
#define NPTS 8192
#define R0_SQ 0.01f
#define THREADS 256
#define JT 8   // j-cols per thread -> each warp writes 1KB contiguous per plane

__global__ __launch_bounds__(THREADS)
void radius_graph_kernel(const float* __restrict__ x, float* __restrict__ out)
{
    // blockIdx.x walks j (fastest) so the concurrently-resident CTA wave writes
    // contiguous row-bands; blockIdx.y walks i.
    const int j0 = (blockIdx.x * THREADS + threadIdx.x) * JT;
    const int i  = blockIdx.y;

    // Broadcast load of the row point (uniform across block)
    const float xi = __ldg(&x[2 * i]);
    const float yi = __ldg(&x[2 * i + 1]);

    // 8 consecutive j-points = 64B = 4x LDG.128
    float px[JT], py[JT];
#pragma unroll
    for (int q = 0; q < JT / 2; ++q) {
        const float4 p = *reinterpret_cast<const float4*>(x + 2 * j0 + 4 * q);
        px[2 * q]     = p.x;  py[2 * q]     = p.y;
        px[2 * q + 1] = p.z;  py[2 * q + 1] = p.w;
    }

    float dist[JT], mask[JT];
#pragma unroll
    for (int k = 0; k < JT; ++k) {
        float dx = px[k] - xi;
        float dy = py[k] - yi;
        // Periodic minimum-image, L=1: dr -= round(dr) (rintf = half-even,
        // matching jnp.round)
        dx -= rintf(dx);
        dy -= rintf(dy);
        const float d2 = fmaf(dx, dx, dy * dy);
        float d;
        asm("sqrt.approx.f32 %0, %1;" : "=f"(d) : "f"(d2));
        dist[k] = d;
        mask[k] = (d2 < R0_SQ && (j0 + k) != i) ? 1.0f : 0.0f;
    }

    const size_t base = (size_t)i * NPTS + (size_t)j0;
    float* dout = out + base;
    float* mout = out + (size_t)NPTS * NPTS + base;
#pragma unroll
    for (int q = 0; q < JT / 4; ++q) {
        __stcs(reinterpret_cast<float4*>(dout + 4 * q),
               make_float4(dist[4 * q], dist[4 * q + 1], dist[4 * q + 2], dist[4 * q + 3]));
    }
#pragma unroll
    for (int q = 0; q < JT / 4; ++q) {
        __stcs(reinterpret_cast<float4*>(mout + 4 * q),
               make_float4(mask[4 * q], mask[4 * q + 1], mask[4 * q + 2], mask[4 * q + 3]));
    }
}

extern "C" void kernel_launch(void* const* d_in, const int* in_sizes, int n_in,
                              void* d_out, int out_size)
{
    (void)n_in; (void)in_sizes; (void)out_size;
    const float* x = (const float*)d_in[0];
    float* out = (float*)d_out;

    dim3 grid(NPTS / (THREADS * JT), NPTS);  // (4, 8192): j fastest, i slow
    radius_graph_kernel<<<grid, THREADS>>>(x, out);
}

// round 5
// speedup vs baseline: 1.8233x; 1.8233x over previous
#include <cuda_runtime.h>
#include <cstddef>

// N=8192, D=2, L=1.0, R0=0.1, no self-loop.
// Output: [0, N*N) dist (f32, row-major), [N*N, 2*N*N) mask as 0.0/1.0.
#define NPTS 8192
#define R0_SQ 0.01f
#define THREADS 256

__global__ __launch_bounds__(THREADS)
void radius_graph_kernel(const float* __restrict__ x, float* __restrict__ out)
{
    // j fastest in the grid: the concurrently-resident CTA wave writes
    // contiguous row-bands. Per-thread tile stays 4 (coalesced STG.128:
    // consecutive lanes write consecutive 16B chunks).
    const int j0 = (blockIdx.x * THREADS + threadIdx.x) * 4;
    const int i  = blockIdx.y;

    // Broadcast load of row point (uniform across block -> L1 broadcast)
    const float xi = __ldg(&x[2 * i]);
    const float yi = __ldg(&x[2 * i + 1]);

    // 4 consecutive j-points = 2x LDG.128
    const float4 p01 = *reinterpret_cast<const float4*>(x + 2 * j0);
    const float4 p23 = *reinterpret_cast<const float4*>(x + 2 * j0 + 4);
    const float px[4] = {p01.x, p01.z, p23.x, p23.z};
    const float py[4] = {p01.y, p01.w, p23.y, p23.w};

    float4 dist4, mask4;
    float* dp = &dist4.x;
    float* mp = &mask4.x;

#pragma unroll
    for (int k = 0; k < 4; ++k) {
        float dx = px[k] - xi;
        float dy = py[k] - yi;
        // Periodic minimum-image, L=1: dr -= round(dr) (rintf = half-even,
        // matching jnp.round)
        dx -= rintf(dx);
        dy -= rintf(dy);
        const float d2 = fmaf(dx, dx, dy * dy);
        float d;
        asm("sqrt.approx.f32 %0, %1;" : "=f"(d) : "f"(d2));
        dp[k] = d;
        mp[k] = (d2 < R0_SQ && (j0 + k) != i) ? 1.0f : 0.0f;
    }

    const size_t base = (size_t)i * NPTS + (size_t)j0;
    // Streaming stores: write-only output, evict-first in L2
    __stcs(reinterpret_cast<float4*>(out + base), dist4);
    __stcs(reinterpret_cast<float4*>(out + (size_t)NPTS * NPTS + base), mask4);
}

extern "C" void kernel_launch(void* const* d_in, const int* in_sizes, int n_in,
                              void* d_out, int out_size)
{
    (void)n_in; (void)in_sizes; (void)out_size;
    const float* x = (const float*)d_in[0];
    float* out = (float*)d_out;

    dim3 grid(NPTS / (THREADS * 4), NPTS);  // (8, 8192): j fastest, i slow
    radius_graph_kernel<<<grid, THREADS>>>(x, out);
}